// round 11
// baseline (speedup 1.0000x reference)
#include <cuda_runtime.h>
#include <cuda_bf16.h>
#include <cstdint>

#define NB  16
#define SEQ 2048
#define DKH 64
#define KSTR 68     // sQ/sK row stride (words): 4 mod 32 -> S/Q frags conflict-free
#define VSTR 72     // sV row stride (words): 8 mod 32 -> PV B-frags conflict-free

// ---------------- device scratch ----------------
__device__ uint32_t g_Qt[NB * SEQ * DKH];            // tf32 bits
__device__ uint32_t g_Kt[NB * SEQ * DKH];
__device__ uint32_t g_Vt[NB * SEQ * DKH];
__device__ uint32_t g_Pt[SEQ * DKH];                 // transposed Krelpos, tf32
__device__ __nv_bfloat16 g_QPb[(size_t)NB * SEQ * SEQ];  // shifted bias [b][s][t]
__device__ float g_O0[(size_t)NB * SEQ * DKH];       // chunk-0 partial O (unnormalized)
__device__ float g_O1[(size_t)NB * SEQ * DKH];       // chunk-1 partial (qi>=8 only)
__device__ float g_l0[NB * SEQ];
__device__ float g_l1[NB * SEQ];
__device__ int g_ctr;

// ---------------- helpers ----------------
__device__ __forceinline__ float f2tf(float x) {
    uint32_t u; asm("cvt.rna.tf32.f32 %0, %1;" : "=r"(u) : "f"(x));
    return __uint_as_float(u);
}
__device__ __forceinline__ uint32_t fu(float x) { return __float_as_uint(x); }

__device__ __forceinline__ uint32_t smem_u32(const void* p) {
    uint32_t a;
    asm("{ .reg .u64 t; cvta.to.shared.u64 t, %1; cvt.u32.u64 %0, t; }" : "=r"(a) : "l"(p));
    return a;
}
__device__ __forceinline__ void mma_tf32(float d[4], const uint32_t a[4], const uint32_t b[2]) {
    asm volatile("mma.sync.aligned.m16n8k8.row.col.f32.tf32.tf32.f32 "
        "{%0,%1,%2,%3}, {%4,%5,%6,%7}, {%8,%9}, {%0,%1,%2,%3};"
        : "+f"(d[0]), "+f"(d[1]), "+f"(d[2]), "+f"(d[3])
        : "r"(a[0]), "r"(a[1]), "r"(a[2]), "r"(a[3]), "r"(b[0]), "r"(b[1]));
}
__device__ __forceinline__ void cpa16(uint32_t s, const void* g) {
    asm volatile("cp.async.cg.shared.global [%0], [%1], 16;" :: "r"(s), "l"(g));
}
#define CP_COMMIT_WAIT() do { \
    asm volatile("cp.async.commit_group;"); \
    asm volatile("cp.async.wait_group 0;" ::: "memory"); } while (0)

// 128x64 f32 tile: gmem row-major -> padded smem, via cp.async (no regs)
__device__ __forceinline__ void cp_tile(uint32_t sbase, const float* gsrc, int tid, int stride) {
#pragma unroll
    for (int k = 0; k < 8; k++) {
        int idx = k * 256 + tid;
        int row = idx >> 4, c4 = (idx & 15) * 4;
        cpa16(sbase + (uint32_t)(row * stride + c4) * 4u, gsrc + row * 64 + c4);
    }
}

// ---------------- prep: tf32 copies of Q/K/V + transposed Pt; counter reset ----
__global__ void prep_kernel(const float* __restrict__ Q, const float* __restrict__ K,
                            const float* __restrict__ V, const float* __restrict__ Kp) {
    int i = blockIdx.x * 256 + threadIdx.x;
    if (i == 0) g_ctr = 0;
    if (i < NB * SEQ * DKH) {
        g_Qt[i] = fu(f2tf(Q[i]));
        g_Kt[i] = fu(f2tf(K[i]));
        g_Vt[i] = fu(f2tf(V[i]));
    }
    if (i < SEQ * DKH) {
        int c = i >> 6, d = i & 63;
        g_Pt[i] = fu(f2tf(Kp[d * SEQ + c]));
    }
}

// ---------------- bias GEMM -> shifted bf16: g_QPb[b][s][t] = Q[b,s].Pt[2047-s+t]
#define BSMEM (2 * 128 * KSTR * 4)

__global__ void __launch_bounds__(256) bias_kernel() {
    const int si = blockIdx.x, ci = blockIdx.y, b = blockIdx.z;
    if (si + ci < 15) return;                 // entirely t<0 under causal mask
    extern __shared__ float sm[];
    uint32_t smb = smem_u32(sm);
    const float* sQf = sm;
    const float* sBf = sm + 128 * KSTR;
    const int tid = threadIdx.x, w = tid >> 5, lane = tid & 31;
    const int g = lane >> 2, j = lane & 3;

    cp_tile(smb, (const float*)g_Qt + ((size_t)b * SEQ + si * 128) * DKH, tid, KSTR);
    cp_tile(smb + 128 * KSTR * 4, (const float*)g_Pt + (size_t)ci * 128 * DKH, tid, KSTR);
    CP_COMMIT_WAIT();
    __syncthreads();

    uint32_t qa[8][4];
#pragma unroll
    for (int k8 = 0; k8 < 8; k8++) {
        const float* ap = sQf + (w * 16 + g) * KSTR + k8 * 8 + j;
        qa[k8][0] = fu(ap[0]);
        qa[k8][1] = fu(ap[8 * KSTR]);
        qa[k8][2] = fu(ap[4]);
        qa[k8][3] = fu(ap[8 * KSTR + 4]);
    }
    const int sr = si * 128 + w * 16 + g;
    __nv_bfloat16* row0 = g_QPb + ((size_t)b * SEQ + sr) * SEQ;
    __nv_bfloat16* row1 = row0 + (size_t)8 * SEQ;
    const int tb0 = ci * 128 + 2 * j + sr - 2047;
    const int tb1 = tb0 + 8;
#pragma unroll
    for (int n = 0; n < 16; n++) {
        float c[4] = {0.f, 0.f, 0.f, 0.f};
#pragma unroll
        for (int k8 = 0; k8 < 8; k8++) {
            const float* bp = sBf + (n * 8 + g) * KSTR + k8 * 8 + j;
            uint32_t bb[2] = {fu(bp[0]), fu(bp[4])};
            mma_tf32(c, qa[k8], bb);
        }
        const int t0 = tb0 + n * 8;
        if (t0 >= 0)     row0[t0]     = __float2bfloat16_rn(c[0]);
        if (t0 + 1 >= 0) row0[t0 + 1] = __float2bfloat16_rn(c[1]);
        const int t1 = tb1 + n * 8;
        if (t1 >= 0)     row1[t1]     = __float2bfloat16_rn(c[2]);
        if (t1 + 1 >= 0) row1[t1 + 1] = __float2bfloat16_rn(c[3]);
    }
}

// ---------------- attention: persistent, fused S->shuffle->PV, split-K ----------
#define ASMEM ((2 * 128 * KSTR + 128 * VSTR) * 4)    // sQ + sK + sV = 106496

__global__ void __launch_bounds__(256, 2) attn_kernel() {
    extern __shared__ float sm[];
    const uint32_t smb = smem_u32(sm);
    const uint32_t sQ = smb, sK = smb + 128 * KSTR * 4, sV = smb + 2 * 128 * KSTR * 4;
    const float* sQf = sm;
    const float* sKf = sm + 128 * KSTR;
    const float* sVf = sm + 2 * 128 * KSTR;
    __shared__ int sWork;
    const int tid = threadIdx.x, w = tid >> 5, lane = tid & 31;
    const int g = lane >> 2, j = lane & 3;
    const int jh = j >> 1, jsel = j & 1;

    for (;;) {
        if (tid == 0) sWork = atomicAdd(&g_ctr, 1);
        __syncthreads();
        const int idx = sWork;
        __syncthreads();                       // all read before next overwrite
        if (idx >= 384) return;
        int qi, ch, b;
        if (idx < 256) { qi = 15 - (idx >> 5); ch = (idx >> 4) & 1; b = idx & 15; }
        else           { int t = idx - 256; qi = 7 - (t >> 4); ch = 0; b = t & 15; }
        int klo = 0, khi = qi + 1;
        if (qi >= 8) { int h = (qi + 2) >> 1; if (ch) klo = h; else khi = h; }

        const int s0 = qi * 128;
        const int r0 = w * 16 + g;
        const int rg = s0 + r0;

        cp_tile(sQ, (const float*)g_Qt + ((size_t)b * SEQ + s0) * DKH, tid, KSTR);
        CP_COMMIT_WAIT();
        __syncthreads();

        uint32_t qa[8][4];
#pragma unroll
        for (int k8 = 0; k8 < 8; k8++) {
            const float* ap = sQf + r0 * KSTR + k8 * 8 + j;
            qa[k8][0] = fu(ap[0]);
            qa[k8][1] = fu(ap[8 * KSTR]);
            qa[k8][2] = fu(ap[4]);
            qa[k8][3] = fu(ap[8 * KSTR + 4]);
        }

        float o[8][4];
#pragma unroll
        for (int n = 0; n < 8; n++) { o[n][0] = o[n][1] = o[n][2] = o[n][3] = 0.f; }
        float l0a = 0.f, l1a = 0.f;
        const __nv_bfloat16* bias0 = g_QPb + ((size_t)(b * SEQ + rg)) * SEQ;
        const __nv_bfloat16* bias1 = bias0 + (size_t)8 * SEQ;

        for (int kt = klo; kt < khi; kt++) {
            const int t0 = kt * 128;
            __syncthreads();                   // prior reads of sK/sV done
            cp_tile(sK, (const float*)g_Kt + ((size_t)b * SEQ + t0) * DKH, tid, KSTR);
            cp_tile(sV, (const float*)g_Vt + ((size_t)b * SEQ + t0) * DKH, tid, VSTR);
            CP_COMMIT_WAIT();
            __syncthreads();

            const bool diag = (kt == qi);
#pragma unroll
            for (int hh = 0; hh < 2; hh++) {
                uint32_t bz0[8], bz1[8];
#pragma unroll
                for (int n = 0; n < 8; n++) {
                    const int col = t0 + (hh * 8 + n) * 8 + 2 * j;
                    bz0[n] = *(const uint32_t*)(bias0 + col);
                    bz1[n] = *(const uint32_t*)(bias1 + col);
                }
#pragma unroll
                for (int n8 = 0; n8 < 8; n8++) {
                    const int n = hh * 8 + n8;
                    float c[4] = {0.f, 0.f, 0.f, 0.f};
#pragma unroll
                    for (int k8 = 0; k8 < 8; k8++) {
                        const float* bp = sKf + (n * 8 + g) * KSTR + k8 * 8 + j;
                        uint32_t bb[2] = {fu(bp[0]), fu(bp[4])};
                        mma_tf32(c, qa[k8], bb);
                    }
                    const float b00 = __uint_as_float(bz0[n8] << 16);
                    const float b01 = __uint_as_float(bz0[n8] & 0xFFFF0000u);
                    const float b10 = __uint_as_float(bz1[n8] << 16);
                    const float b11 = __uint_as_float(bz1[n8] & 0xFFFF0000u);
                    float e0 = __expf((c[0] + b00) * 0.125f);
                    float e1 = __expf((c[1] + b01) * 0.125f);
                    float e2 = __expf((c[2] + b10) * 0.125f);
                    float e3 = __expf((c[3] + b11) * 0.125f);
                    if (diag) {
                        const int tc = t0 + n * 8 + 2 * j;
                        e0 = (tc     <= rg    ) ? e0 : 0.f;
                        e1 = (tc + 1 <= rg    ) ? e1 : 0.f;
                        e2 = (tc     <= rg + 8) ? e2 : 0.f;
                        e3 = (tc + 1 <= rg + 8) ? e3 : 0.f;
                    }
                    l0a += e0 + e1;
                    l1a += e2 + e3;
                    // C-frag -> A-frag transpose within 4-lane groups
                    float lo, hi, a0, a1, a2, a3;
                    lo = __shfl_sync(0xFFFFFFFFu, e0, jh, 4);
                    hi = __shfl_sync(0xFFFFFFFFu, e1, jh, 4);
                    a0 = jsel ? hi : lo;
                    lo = __shfl_sync(0xFFFFFFFFu, e2, jh, 4);
                    hi = __shfl_sync(0xFFFFFFFFu, e3, jh, 4);
                    a1 = jsel ? hi : lo;
                    lo = __shfl_sync(0xFFFFFFFFu, e0, jh + 2, 4);
                    hi = __shfl_sync(0xFFFFFFFFu, e1, jh + 2, 4);
                    a2 = jsel ? hi : lo;
                    lo = __shfl_sync(0xFFFFFFFFu, e2, jh + 2, 4);
                    hi = __shfl_sync(0xFFFFFFFFu, e3, jh + 2, 4);
                    a3 = jsel ? hi : lo;
                    uint32_t aa[4] = {fu(f2tf(a0)), fu(f2tf(a1)), fu(f2tf(a2)), fu(f2tf(a3))};
                    // O += P(:, 8n..8n+7) . V(8n..8n+7, :)
#pragma unroll
                    for (int np = 0; np < 8; np++) {
                        const float* bp = sVf + (n * 8 + j) * VSTR + np * 8 + g;
                        uint32_t bb[2] = {fu(bp[0]), fu(bp[4 * VSTR])};
                        mma_tf32(o[np], aa, bb);
                    }
                }
            }
        }

        l0a += __shfl_xor_sync(0xFFFFFFFFu, l0a, 1);
        l0a += __shfl_xor_sync(0xFFFFFFFFu, l0a, 2);
        l1a += __shfl_xor_sync(0xFFFFFFFFu, l1a, 1);
        l1a += __shfl_xor_sync(0xFFFFFFFFu, l1a, 2);

        float* Ob = (ch ? g_O1 : g_O0) + ((size_t)(b * SEQ + rg)) * DKH;
        float* lb = ch ? g_l1 : g_l0;
        if (j == 0) {
            lb[b * SEQ + rg] = l0a;
            lb[b * SEQ + rg + 8] = l1a;
        }
#pragma unroll
        for (int np = 0; np < 8; np++) {
            *(float2*)(Ob + np * 8 + 2 * j) = make_float2(o[np][0], o[np][1]);
            *(float2*)(Ob + 8 * DKH + np * 8 + 2 * j) = make_float2(o[np][2], o[np][3]);
        }
    }
}

// ---------------- final combine + normalize ----------------
__global__ void final_kernel(float* __restrict__ Out) {
    int i = blockIdx.x * 256 + threadIdx.x;    // indexes float4 units
    int row = i >> 4;                          // b*SEQ + s
    int c4 = (i & 15) * 4;
    int s = row & (SEQ - 1);
    float l = g_l0[row];
    float4 o = *(const float4*)(g_O0 + (size_t)row * DKH + c4);
    if (s >= 1024) {                           // qi >= 8 -> split item
        l += g_l1[row];
        float4 o1 = *(const float4*)(g_O1 + (size_t)row * DKH + c4);
        o.x += o1.x; o.y += o1.y; o.z += o1.z; o.w += o1.w;
    }
    const float inv = 1.0f / l;
    o.x *= inv; o.y *= inv; o.z *= inv; o.w *= inv;
    *(float4*)(Out + (size_t)row * DKH + c4) = o;
}

extern "C" void kernel_launch(void* const* d_in, const int* in_sizes, int n_in,
                              void* d_out, int out_size) {
    const float* Q  = (const float*)d_in[0];
    const float* K  = (const float*)d_in[1];
    const float* V  = (const float*)d_in[2];
    const float* Kp = (const float*)d_in[3];
    float* Out      = (float*)d_out;

    cudaFuncSetAttribute(bias_kernel, cudaFuncAttributeMaxDynamicSharedMemorySize, BSMEM);
    cudaFuncSetAttribute(attn_kernel, cudaFuncAttributeMaxDynamicSharedMemorySize, ASMEM);

    prep_kernel<<<(NB * SEQ * DKH + 255) / 256, 256>>>(Q, K, V, Kp);
    dim3 bg(16, 16, 16);
    bias_kernel<<<bg, 256, BSMEM>>>();
    attn_kernel<<<296, 256, ASMEM>>>();
    final_kernel<<<(NB * SEQ * DKH / 4 + 255) / 256, 256>>>(Out);
}

// round 12
// speedup vs baseline: 1.4380x; 1.4380x over previous
#include <cuda_runtime.h>
#include <cuda_bf16.h>
#include <cstdint>

#define NB  16
#define SEQ 2048
#define DKH 64
#define KSTR 68     // sK/sP row stride (words)
#define VSTR 72     // sV row stride (words)

// ---------------- device scratch ----------------
__device__ uint32_t g_Qt[NB * SEQ * DKH];            // tf32 bits
__device__ uint32_t g_Kt[NB * SEQ * DKH];
__device__ uint32_t g_Vt[NB * SEQ * DKH];
__device__ uint32_t g_Pt[SEQ * DKH];                 // transposed Krelpos, tf32
__device__ __nv_bfloat16 g_QPb[(size_t)NB * SEQ * SEQ];  // shifted bias [b][s][t]
__device__ float g_O0[(size_t)NB * SEQ * DKH];
__device__ float g_O1[(size_t)NB * SEQ * DKH];
__device__ float g_l0[NB * SEQ];
__device__ float g_l1[NB * SEQ];
__device__ int g_ctr;

// ---------------- helpers ----------------
__device__ __forceinline__ float f2tf(float x) {
    uint32_t u; asm("cvt.rna.tf32.f32 %0, %1;" : "=r"(u) : "f"(x));
    return __uint_as_float(u);
}
__device__ __forceinline__ uint32_t fu(float x) { return __float_as_uint(x); }
__device__ __forceinline__ uint32_t smem_u32(const void* p) {
    uint32_t a;
    asm("{ .reg .u64 t; cvta.to.shared.u64 t, %1; cvt.u32.u64 %0, t; }" : "=r"(a) : "l"(p));
    return a;
}
__device__ __forceinline__ void mma_tf32(float d[4], const uint32_t a[4], const uint32_t b[2]) {
    asm volatile("mma.sync.aligned.m16n8k8.row.col.f32.tf32.tf32.f32 "
        "{%0,%1,%2,%3}, {%4,%5,%6,%7}, {%8,%9}, {%0,%1,%2,%3};"
        : "+f"(d[0]), "+f"(d[1]), "+f"(d[2]), "+f"(d[3])
        : "r"(a[0]), "r"(a[1]), "r"(a[2]), "r"(a[3]), "r"(b[0]), "r"(b[1]));
}
__device__ __forceinline__ void cpa16(uint32_t s, const void* g) {
    asm volatile("cp.async.cg.shared.global [%0], [%1], 16;" :: "r"(s), "l"(g));
}
#define CP_COMMIT_WAIT() do { \
    asm volatile("cp.async.commit_group;"); \
    asm volatile("cp.async.wait_group 0;" ::: "memory"); } while (0)

__device__ __forceinline__ void cp_tile(uint32_t sbase, const float* gsrc, int tid, int stride) {
#pragma unroll
    for (int k = 0; k < 8; k++) {
        int idx = k * 256 + tid;
        int row = idx >> 4, c4 = (idx & 15) * 4;
        cpa16(sbase + (uint32_t)(row * stride + c4) * 4u, gsrc + row * 64 + c4);
    }
}

// ---------------- prep ----------------
__global__ void prep_kernel(const float* __restrict__ Q, const float* __restrict__ K,
                            const float* __restrict__ V, const float* __restrict__ Kp) {
    int i = blockIdx.x * 256 + threadIdx.x;
    if (i == 0) g_ctr = 0;
    if (i < NB * SEQ * DKH) {
        g_Qt[i] = fu(f2tf(Q[i]));
        g_Kt[i] = fu(f2tf(K[i]));
        g_Vt[i] = fu(f2tf(V[i]));
    }
    if (i < SEQ * DKH) {
        int c = i >> 6, d = i & 63;
        g_Pt[i] = fu(f2tf(Kp[d * SEQ + c]));
    }
}

// ---------------- bias GEMM -> shifted bf16 ----------------
#define BSMEM (2 * 128 * KSTR * 4)

__global__ void __launch_bounds__(256) bias_kernel() {
    const int si = blockIdx.x, ci = blockIdx.y, b = blockIdx.z;
    if (si + ci < 15) return;
    extern __shared__ float sm[];
    uint32_t smb = smem_u32(sm);
    const float* sQf = sm;
    const float* sBf = sm + 128 * KSTR;
    const int tid = threadIdx.x, w = tid >> 5, lane = tid & 31;
    const int g = lane >> 2, j = lane & 3;

    cp_tile(smb, (const float*)g_Qt + ((size_t)b * SEQ + si * 128) * DKH, tid, KSTR);
    cp_tile(smb + 128 * KSTR * 4, (const float*)g_Pt + (size_t)ci * 128 * DKH, tid, KSTR);
    CP_COMMIT_WAIT();
    __syncthreads();

    uint32_t qa[8][4];
#pragma unroll
    for (int k8 = 0; k8 < 8; k8++) {
        const float* ap = sQf + (w * 16 + g) * KSTR + k8 * 8 + j;
        qa[k8][0] = fu(ap[0]);
        qa[k8][1] = fu(ap[8 * KSTR]);
        qa[k8][2] = fu(ap[4]);
        qa[k8][3] = fu(ap[8 * KSTR + 4]);
    }
    const int sr = si * 128 + w * 16 + g;
    __nv_bfloat16* row0 = g_QPb + ((size_t)b * SEQ + sr) * SEQ;
    __nv_bfloat16* row1 = row0 + (size_t)8 * SEQ;
    const int tb0 = ci * 128 + 2 * j + sr - 2047;
    const int tb1 = tb0 + 8;
#pragma unroll
    for (int n = 0; n < 16; n++) {
        float c[4] = {0.f, 0.f, 0.f, 0.f};
#pragma unroll
        for (int k8 = 0; k8 < 8; k8++) {
            const float* bp = sBf + (n * 8 + g) * KSTR + k8 * 8 + j;
            uint32_t bb[2] = {fu(bp[0]), fu(bp[4])};
            mma_tf32(c, qa[k8], bb);
        }
        const int t0 = tb0 + n * 8;
        if (t0 >= 0)     row0[t0]     = __float2bfloat16_rn(c[0]);
        if (t0 + 1 >= 0) row0[t0 + 1] = __float2bfloat16_rn(c[1]);
        const int t1 = tb1 + n * 8;
        if (t1 >= 0)     row1[t1]     = __float2bfloat16_rn(c[2]);
        if (t1 + 1 >= 0) row1[t1 + 1] = __float2bfloat16_rn(c[3]);
    }
}

// ---------------- attention: persistent, split-K, 2 CTAs/SM, half-tile sP ----
#define ASMEM ((128 * KSTR + 128 * VSTR + 128 * KSTR) * 4)   // 106496

__global__ void __launch_bounds__(256, 2) attn_kernel() {
    extern __shared__ float sm[];
    const uint32_t smb = smem_u32(sm);
    const uint32_t sK = smb, sV = smb + 128 * KSTR * 4;
    const float* sKf = sm;
    const float* sVf = sm + 128 * KSTR;
    float* sPf = sm + 128 * KSTR + 128 * VSTR;
    __shared__ int sWork;
    const int tid = threadIdx.x, w = tid >> 5, lane = tid & 31;
    const int g = lane >> 2, j = lane & 3;

    for (;;) {
        if (tid == 0) sWork = atomicAdd(&g_ctr, 1);
        __syncthreads();
        const int idx = sWork;
        __syncthreads();
        if (idx >= 384) return;
        int qi, ch, b;
        if (idx < 256) { qi = 15 - (idx >> 5); ch = (idx >> 4) & 1; b = idx & 15; }
        else           { int t = idx - 256; qi = 7 - (t >> 4); ch = 0; b = t & 15; }
        int klo = 0, khi = qi + 1;
        if (qi >= 8) { int h2 = (qi + 2) >> 1; if (ch) klo = h2; else khi = h2; }

        const int s0 = qi * 128;
        const int r0 = w * 16 + g;
        const int rg = s0 + r0;

        // Q fragments straight from gmem (once per item)
        uint32_t qa[8][4];
        {
            const uint32_t* Qb = g_Qt + ((size_t)(b * SEQ + rg)) * DKH;
#pragma unroll
            for (int k8 = 0; k8 < 8; k8++) {
                qa[k8][0] = Qb[k8 * 8 + j];
                qa[k8][1] = Qb[8 * DKH + k8 * 8 + j];
                qa[k8][2] = Qb[k8 * 8 + j + 4];
                qa[k8][3] = Qb[8 * DKH + k8 * 8 + j + 4];
            }
        }

        float o[8][4];
#pragma unroll
        for (int n = 0; n < 8; n++) { o[n][0] = o[n][1] = o[n][2] = o[n][3] = 0.f; }
        float l0a = 0.f, l1a = 0.f;
        const __nv_bfloat16* bias0 = g_QPb + ((size_t)(b * SEQ + rg)) * SEQ;
        const __nv_bfloat16* bias1 = bias0 + (size_t)8 * SEQ;

        for (int kt = klo; kt < khi; kt++) {
            const int t0 = kt * 128;
            cp_tile(sK, (const float*)g_Kt + ((size_t)(b * SEQ + t0)) * DKH, tid, KSTR);
            cp_tile(sV, (const float*)g_Vt + ((size_t)(b * SEQ + t0)) * DKH, tid, VSTR);
            CP_COMMIT_WAIT();
            __syncthreads();

            const bool diag = (kt == qi);
#pragma unroll
            for (int hh = 0; hh < 2; hh++) {
                // ---- S half: 8 n-blocks -> exp -> sP (64 cols)
                uint32_t bz0[8], bz1[8];
#pragma unroll
                for (int n8 = 0; n8 < 8; n8++) {
                    const int col = t0 + (hh * 8 + n8) * 8 + 2 * j;
                    bz0[n8] = *(const uint32_t*)(bias0 + col);
                    bz1[n8] = *(const uint32_t*)(bias1 + col);
                }
#pragma unroll
                for (int n8 = 0; n8 < 8; n8++) {
                    const int n = hh * 8 + n8;
                    float c[4] = {0.f, 0.f, 0.f, 0.f};
#pragma unroll
                    for (int k8 = 0; k8 < 8; k8++) {
                        const float* bp = sKf + (n * 8 + g) * KSTR + k8 * 8 + j;
                        uint32_t bb[2] = {fu(bp[0]), fu(bp[4])};
                        mma_tf32(c, qa[k8], bb);
                    }
                    const float b00 = __uint_as_float(bz0[n8] << 16);
                    const float b01 = __uint_as_float(bz0[n8] & 0xFFFF0000u);
                    const float b10 = __uint_as_float(bz1[n8] << 16);
                    const float b11 = __uint_as_float(bz1[n8] & 0xFFFF0000u);
                    float e0 = __expf((c[0] + b00) * 0.125f);
                    float e1 = __expf((c[1] + b01) * 0.125f);
                    float e2 = __expf((c[2] + b10) * 0.125f);
                    float e3 = __expf((c[3] + b11) * 0.125f);
                    if (diag) {
                        const int tc = t0 + n * 8 + 2 * j;
                        e0 = (tc     <= rg    ) ? e0 : 0.f;
                        e1 = (tc + 1 <= rg    ) ? e1 : 0.f;
                        e2 = (tc     <= rg + 8) ? e2 : 0.f;
                        e3 = (tc + 1 <= rg + 8) ? e3 : 0.f;
                    }
                    l0a += e0 + e1;
                    l1a += e2 + e3;
                    *(float2*)(sPf + r0 * KSTR + n8 * 8 + 2 * j) =
                        make_float2(f2tf(e0), f2tf(e1));
                    *(float2*)(sPf + (r0 + 8) * KSTR + n8 * 8 + 2 * j) =
                        make_float2(f2tf(e2), f2tf(e3));
                }
                __syncthreads();   // sP half ready

                // ---- PV half: O += P(:,64h..64h+63) . V(64h..64h+63,:)
#pragma unroll
                for (int k8 = 0; k8 < 8; k8++) {
                    const float* ap = sPf + r0 * KSTR + k8 * 8 + j;
                    uint32_t aa[4] = {fu(ap[0]), fu(ap[8 * KSTR]),
                                      fu(ap[4]), fu(ap[8 * KSTR + 4])};
#pragma unroll
                    for (int np = 0; np < 8; np++) {
                        const float* bp = sVf + (hh * 64 + k8 * 8 + j) * VSTR + np * 8 + g;
                        uint32_t bb[2] = {fu(bp[0]), fu(bp[4 * VSTR])};
                        mma_tf32(o[np], aa, bb);
                    }
                }
                __syncthreads();   // sP reusable for next half / next tile
            }
        }

        l0a += __shfl_xor_sync(0xFFFFFFFFu, l0a, 1);
        l0a += __shfl_xor_sync(0xFFFFFFFFu, l0a, 2);
        l1a += __shfl_xor_sync(0xFFFFFFFFu, l1a, 1);
        l1a += __shfl_xor_sync(0xFFFFFFFFu, l1a, 2);

        float* Ob = (ch ? g_O1 : g_O0) + ((size_t)(b * SEQ + rg)) * DKH;
        float* lb = ch ? g_l1 : g_l0;
        if (j == 0) {
            lb[b * SEQ + rg] = l0a;
            lb[b * SEQ + rg + 8] = l1a;
        }
#pragma unroll
        for (int np = 0; np < 8; np++) {
            *(float2*)(Ob + np * 8 + 2 * j) = make_float2(o[np][0], o[np][1]);
            *(float2*)(Ob + 8 * DKH + np * 8 + 2 * j) = make_float2(o[np][2], o[np][3]);
        }
    }
}

// ---------------- final combine + normalize ----------------
__global__ void final_kernel(float* __restrict__ Out) {
    int i = blockIdx.x * 256 + threadIdx.x;
    int row = i >> 4;
    int c4 = (i & 15) * 4;
    int s = row & (SEQ - 1);
    float l = g_l0[row];
    float4 o = *(const float4*)(g_O0 + (size_t)row * DKH + c4);
    if (s >= 1024) {
        l += g_l1[row];
        float4 o1 = *(const float4*)(g_O1 + (size_t)row * DKH + c4);
        o.x += o1.x; o.y += o1.y; o.z += o1.z; o.w += o1.w;
    }
    const float inv = 1.0f / l;
    o.x *= inv; o.y *= inv; o.z *= inv; o.w *= inv;
    *(float4*)(Out + (size_t)row * DKH + c4) = o;
}

extern "C" void kernel_launch(void* const* d_in, const int* in_sizes, int n_in,
                              void* d_out, int out_size) {
    const float* Q  = (const float*)d_in[0];
    const float* K  = (const float*)d_in[1];
    const float* V  = (const float*)d_in[2];
    const float* Kp = (const float*)d_in[3];
    float* Out      = (float*)d_out;

    cudaFuncSetAttribute(bias_kernel, cudaFuncAttributeMaxDynamicSharedMemorySize, BSMEM);
    cudaFuncSetAttribute(attn_kernel, cudaFuncAttributeMaxDynamicSharedMemorySize, ASMEM);

    prep_kernel<<<(NB * SEQ * DKH + 255) / 256, 256>>>(Q, K, V, Kp);
    dim3 bg(16, 16, 16);
    bias_kernel<<<bg, 256, BSMEM>>>();
    attn_kernel<<<296, 256, ASMEM>>>();
    final_kernel<<<(NB * SEQ * DKH / 4 + 255) / 256, 256>>>(Out);
}